// round 1
// baseline (speedup 1.0000x reference)
#include <cuda_runtime.h>

// LSTM_558345748830: 2-layer LSTM (B=4096, T=512, I=1, H=32) + FC head.
// Fully fused: both layers + FC in one persistent-per-block kernel.
// Block = 128 threads (one per gate row), NB=8 batch elements per block.
// All recurrent weights live in registers (96 floats/thread); states in smem.

#define Tn 512
#define Hn 32
#define Gn 128   // 4*H
#define NB 8
#define NTHREADS 128
#define Bn 4096

__device__ __forceinline__ float sigf(float x) {
    // sigmoid via EX2-based expf; exact at extremes (exp->0 or inf).
    return __fdividef(1.0f, 1.0f + __expf(-x));
}

__device__ __forceinline__ float tanh_fast(float x) {
    // tanh(|x|) = (1 - e^{-2|x|}) / (1 + e^{-2|x|}), sign restored.
    float ax = fabsf(x);
    float e  = __expf(-2.0f * ax);
    float r  = __fdividef(1.0f - e, 1.0f + e);
    return copysignf(r, x);
}

__global__ __launch_bounds__(NTHREADS, 3)
void lstm_fused_kernel(const float* __restrict__ x,
                       const float* __restrict__ w_ih_0, const float* __restrict__ w_hh_0,
                       const float* __restrict__ b_ih_0, const float* __restrict__ b_hh_0,
                       const float* __restrict__ w_ih_1, const float* __restrict__ w_hh_1,
                       const float* __restrict__ b_ih_1, const float* __restrict__ b_hh_1,
                       const float* __restrict__ fc_w,   const float* __restrict__ fc_b,
                       float* __restrict__ out)
{
    __shared__ float xs[NB][Tn];       // 16 KB: input slab for this block
    __shared__ float h1s[NB][Hn];      // layer-1 hidden state
    __shared__ float h2s[NB][Hn];      // layer-2 hidden state
    __shared__ float gates[NB][Gn];    // gate pre-activations staging

    const int tid = threadIdx.x;
    const int r   = tid;               // gate row 0..127 (i:0-31, f:32-63, g:64-95, o:96-127)
    const int gq  = tid >> 5;          // warp id 0..3 -> which batch residue this thread updates
    const int j   = tid & 31;          // hidden unit within gate
    const int b0  = blockIdx.x * NB;

    // ---- load per-row weights into registers (row r of each weight matrix) ----
    float whh0[Hn], wih1[Hn], whh1[Hn];
    {
        const float4* p0 = (const float4*)(w_hh_0 + r * Hn);
        const float4* p1 = (const float4*)(w_ih_1 + r * Hn);
        const float4* p2 = (const float4*)(w_hh_1 + r * Hn);
        #pragma unroll
        for (int q = 0; q < Hn / 4; q++) {
            float4 a = p0[q];
            whh0[4*q] = a.x; whh0[4*q+1] = a.y; whh0[4*q+2] = a.z; whh0[4*q+3] = a.w;
            float4 b = p1[q];
            wih1[4*q] = b.x; wih1[4*q+1] = b.y; wih1[4*q+2] = b.z; wih1[4*q+3] = b.w;
            float4 c = p2[q];
            whh1[4*q] = c.x; whh1[4*q+1] = c.y; whh1[4*q+2] = c.z; whh1[4*q+3] = c.w;
        }
    }
    const float wih0_r = w_ih_0[r];                 // w_ih_0 is [128,1]
    const float bias0  = b_ih_0[r] + b_hh_0[r];     // biases fused (matches reference xg)
    const float bias1  = b_ih_1[r] + b_hh_1[r];

    // ---- preload x slab (contiguous NB*Tn floats) into shared, coalesced ----
    {
        const float4* src = (const float4*)(x + (size_t)b0 * Tn);
        float4* dst = (float4*)&xs[0][0];
        #pragma unroll
        for (int i = tid; i < NB * Tn / 4; i += NTHREADS) dst[i] = src[i];
    }
    // ---- init states ----
    for (int i = tid; i < NB * Hn; i += NTHREADS) {
        ((float*)h1s)[i] = 0.0f;
        ((float*)h2s)[i] = 0.0f;
    }
    float c1[NB / 4], c2[NB / 4];
    #pragma unroll
    for (int e = 0; e < NB / 4; e++) { c1[e] = 0.0f; c2[e] = 0.0f; }
    __syncthreads();

    // ================= main recurrence =================
    for (int t = 0; t < Tn; t++) {
        // ---- Phase A: layer-1 gate pre-activations for all NB elements ----
        #pragma unroll
        for (int b = 0; b < NB; b++) {
            float acc = fmaf(wih0_r, xs[b][t], bias0);
            const float4* hv = (const float4*)&h1s[b][0];   // broadcast reads
            #pragma unroll
            for (int q = 0; q < 8; q++) {
                float4 h4 = hv[q];
                acc = fmaf(whh0[4*q+0], h4.x, acc);
                acc = fmaf(whh0[4*q+1], h4.y, acc);
                acc = fmaf(whh0[4*q+2], h4.z, acc);
                acc = fmaf(whh0[4*q+3], h4.w, acc);
            }
            gates[b][r] = acc;
        }
        __syncthreads();

        // ---- Phase B: layer-1 elementwise update ----
        #pragma unroll
        for (int e = 0; e < NB / 4; e++) {
            const int b = gq + 4 * e;
            float gi = gates[b][j];
            float gf = gates[b][Hn + j];
            float gg = gates[b][2 * Hn + j];
            float go = gates[b][3 * Hn + j];
            float i_ = sigf(gi);
            float f_ = sigf(gf);
            float g_ = tanh_fast(gg);
            float o_ = sigf(go);
            float c  = fmaf(f_, c1[e], i_ * g_);
            c1[e] = c;
            h1s[b][j] = o_ * tanh_fast(c);
        }
        __syncthreads();

        // ---- Phase C: layer-2 gate pre-activations ----
        #pragma unroll
        for (int b = 0; b < NB; b++) {
            float acc = bias1;
            const float4* h1v = (const float4*)&h1s[b][0];
            const float4* h2v = (const float4*)&h2s[b][0];
            #pragma unroll
            for (int q = 0; q < 8; q++) {
                float4 a4 = h1v[q];
                float4 b4 = h2v[q];
                acc = fmaf(wih1[4*q+0], a4.x, acc);
                acc = fmaf(wih1[4*q+1], a4.y, acc);
                acc = fmaf(wih1[4*q+2], a4.z, acc);
                acc = fmaf(wih1[4*q+3], a4.w, acc);
                acc = fmaf(whh1[4*q+0], b4.x, acc);
                acc = fmaf(whh1[4*q+1], b4.y, acc);
                acc = fmaf(whh1[4*q+2], b4.z, acc);
                acc = fmaf(whh1[4*q+3], b4.w, acc);
            }
            gates[b][r] = acc;
        }
        __syncthreads();

        // ---- Phase D: layer-2 elementwise update ----
        #pragma unroll
        for (int e = 0; e < NB / 4; e++) {
            const int b = gq + 4 * e;
            float gi = gates[b][j];
            float gf = gates[b][Hn + j];
            float gg = gates[b][2 * Hn + j];
            float go = gates[b][3 * Hn + j];
            float i_ = sigf(gi);
            float f_ = sigf(gf);
            float g_ = tanh_fast(gg);
            float o_ = sigf(go);
            float c  = fmaf(f_, c2[e], i_ * g_);
            c2[e] = c;
            h2s[b][j] = o_ * tanh_fast(c);
        }
        __syncthreads();
    }

    // ---- FC head: out[b] = h2_last . fc_w + fc_b ----
    if (tid < NB) {
        float acc = fc_b[0];
        #pragma unroll
        for (int k = 0; k < Hn; k++) acc = fmaf(h2s[tid][k], fc_w[k], acc);
        out[b0 + tid] = acc;
    }
}

extern "C" void kernel_launch(void* const* d_in, const int* in_sizes, int n_in,
                              void* d_out, int out_size)
{
    const float* x      = (const float*)d_in[0];
    const float* w_ih_0 = (const float*)d_in[1];
    const float* w_hh_0 = (const float*)d_in[2];
    const float* b_ih_0 = (const float*)d_in[3];
    const float* b_hh_0 = (const float*)d_in[4];
    const float* w_ih_1 = (const float*)d_in[5];
    const float* w_hh_1 = (const float*)d_in[6];
    const float* b_ih_1 = (const float*)d_in[7];
    const float* b_hh_1 = (const float*)d_in[8];
    const float* fc_w   = (const float*)d_in[9];
    const float* fc_b   = (const float*)d_in[10];
    float* out = (float*)d_out;

    dim3 grid(Bn / NB);   // 512 blocks
    dim3 block(NTHREADS); // 128 threads
    lstm_fused_kernel<<<grid, block>>>(x, w_ih_0, w_hh_0, b_ih_0, b_hh_0,
                                       w_ih_1, w_hh_1, b_ih_1, b_hh_1,
                                       fc_w, fc_b, out);
}

// round 2
// speedup vs baseline: 1.1762x; 1.1762x over previous
#include <cuda_runtime.h>

// LSTM_558345748830: 2-layer LSTM (B=4096, T=512, I=1, H=32) + FC head.
// v2: single-wave grid (256 blocks x 256 thr, 2 blocks/SM), split-K half-warp
// gate rows, 3 barriers/step, MUFU.TANH activations.

#define Tn 512
#define Hn 32
#define Gn 128      // 4*H
#define NB 16       // batches per block
#define NT 256      // threads per block
#define Bn 4096

__device__ __forceinline__ float tanhap(float x) {
    float y;
    asm("tanh.approx.f32 %0, %1;" : "=f"(y) : "f"(x));
    return y;
}
__device__ __forceinline__ float sigap(float x) {
    // sigmoid(x) = 0.5 * tanh(0.5x) + 0.5
    return fmaf(tanhap(0.5f * x), 0.5f, 0.5f);
}

__global__ __launch_bounds__(NT, 2)
void lstm_fused_v2(const float* __restrict__ x,
                   const float* __restrict__ w_ih_0, const float* __restrict__ w_hh_0,
                   const float* __restrict__ b_ih_0, const float* __restrict__ b_hh_0,
                   const float* __restrict__ w_ih_1, const float* __restrict__ w_hh_1,
                   const float* __restrict__ b_ih_1, const float* __restrict__ b_hh_1,
                   const float* __restrict__ fc_w,   const float* __restrict__ fc_b,
                   float* __restrict__ out)
{
    __shared__ float g1[NB][Gn];     // layer-1 gate preacts (8 KB)
    __shared__ float g2[NB][Gn];     // layer-2 gate preacts (8 KB)
    __shared__ float h1s[NB][Hn];    // layer-1 hidden (2 KB)
    __shared__ float h2s[NB][Hn];    // layer-2 hidden (2 KB)

    const int tid  = threadIdx.x;
    const int lane = tid & 31;
    const int warp = tid >> 5;             // 0..7
    // GEMM role: gate row r in 0..127, k-half kh in {0,1}
    const int r  = warp * 16 + (lane & 15);
    const int kh = lane >> 4;
    const int kb = kh * 16;                // k base (0 or 16)
    const int b0 = blockIdx.x * NB;

    // ---- per-thread weight slices (16 floats per matrix) ----
    float whh0[16], wih1[16], whh1[16];
    {
        const float4* p0 = (const float4*)(w_hh_0 + r * Hn + kb);
        const float4* p1 = (const float4*)(w_ih_1 + r * Hn + kb);
        const float4* p2 = (const float4*)(w_hh_1 + r * Hn + kb);
        #pragma unroll
        for (int q = 0; q < 4; q++) {
            float4 a = p0[q];
            whh0[4*q+0]=a.x; whh0[4*q+1]=a.y; whh0[4*q+2]=a.z; whh0[4*q+3]=a.w;
            float4 b = p1[q];
            wih1[4*q+0]=b.x; wih1[4*q+1]=b.y; wih1[4*q+2]=b.z; wih1[4*q+3]=b.w;
            float4 c = p2[q];
            whh1[4*q+0]=c.x; whh1[4*q+1]=c.y; whh1[4*q+2]=c.z; whh1[4*q+3]=c.w;
        }
    }
    const float wih0_r = w_ih_0[r];
    const float bias0  = b_ih_0[r] + b_hh_0[r];
    const float bias1  = b_ih_1[r] + b_hh_1[r];

    // Elementwise role: thread handles (eb0, ej) and (eb1, ej)
    const int ej  = lane;
    const int eb0 = warp;
    const int eb1 = warp + 8;
    float c1a = 0.f, c1b = 0.f, c2a = 0.f, c2b = 0.f;

    // ---- init states ----
    for (int i = tid; i < NB * Hn; i += NT) {
        ((float*)h1s)[i] = 0.0f;
        ((float*)h2s)[i] = 0.0f;
    }
    __syncthreads();

    const float* xrow = x + (size_t)b0 * Tn;   // x[b0+b][t] = xrow[b*Tn + t]

    for (int t = 0; t < Tn; t++) {
        // ---- Phase A: layer-1 gate preacts (split-K, half-warp reduce) ----
        #pragma unroll 4
        for (int b = 0; b < NB; b++) {
            float acc = (kh == 0) ? fmaf(wih0_r, __ldg(&xrow[b * Tn + t]), bias0)
                                  : 0.0f;
            const float4* hv = (const float4*)&h1s[b][kb];
            float4 p = hv[0], q = hv[1], u = hv[2], v = hv[3];
            acc = fmaf(whh0[ 0], p.x, acc); acc = fmaf(whh0[ 1], p.y, acc);
            acc = fmaf(whh0[ 2], p.z, acc); acc = fmaf(whh0[ 3], p.w, acc);
            acc = fmaf(whh0[ 4], q.x, acc); acc = fmaf(whh0[ 5], q.y, acc);
            acc = fmaf(whh0[ 6], q.z, acc); acc = fmaf(whh0[ 7], q.w, acc);
            acc = fmaf(whh0[ 8], u.x, acc); acc = fmaf(whh0[ 9], u.y, acc);
            acc = fmaf(whh0[10], u.z, acc); acc = fmaf(whh0[11], u.w, acc);
            acc = fmaf(whh0[12], v.x, acc); acc = fmaf(whh0[13], v.y, acc);
            acc = fmaf(whh0[14], v.z, acc); acc = fmaf(whh0[15], v.w, acc);
            acc += __shfl_xor_sync(0xffffffffu, acc, 16);
            if (kh == 0) g1[b][r] = acc;
        }
        __syncthreads();

        // ---- Phase B: layer-1 elementwise (each thread: 2 (b,j) pairs) ----
        {
            float gi = g1[eb0][ej], gf = g1[eb0][Hn + ej];
            float gg = g1[eb0][2*Hn + ej], go = g1[eb0][3*Hn + ej];
            float i_ = sigap(gi), f_ = sigap(gf), g_ = tanhap(gg), o_ = sigap(go);
            c1a = fmaf(f_, c1a, i_ * g_);
            h1s[eb0][ej] = o_ * tanhap(c1a);

            gi = g1[eb1][ej]; gf = g1[eb1][Hn + ej];
            gg = g1[eb1][2*Hn + ej]; go = g1[eb1][3*Hn + ej];
            i_ = sigap(gi); f_ = sigap(gf); g_ = tanhap(gg); o_ = sigap(go);
            c1b = fmaf(f_, c1b, i_ * g_);
            h1s[eb1][ej] = o_ * tanhap(c1b);
        }
        __syncthreads();

        // ---- Phase C: layer-2 gate preacts ----
        #pragma unroll 4
        for (int b = 0; b < NB; b++) {
            float acc = (kh == 0) ? bias1 : 0.0f;
            const float4* av = (const float4*)&h1s[b][kb];
            const float4* bv = (const float4*)&h2s[b][kb];
            float4 p = av[0], q = av[1], u = av[2], v = av[3];
            acc = fmaf(wih1[ 0], p.x, acc); acc = fmaf(wih1[ 1], p.y, acc);
            acc = fmaf(wih1[ 2], p.z, acc); acc = fmaf(wih1[ 3], p.w, acc);
            acc = fmaf(wih1[ 4], q.x, acc); acc = fmaf(wih1[ 5], q.y, acc);
            acc = fmaf(wih1[ 6], q.z, acc); acc = fmaf(wih1[ 7], q.w, acc);
            acc = fmaf(wih1[ 8], u.x, acc); acc = fmaf(wih1[ 9], u.y, acc);
            acc = fmaf(wih1[10], u.z, acc); acc = fmaf(wih1[11], u.w, acc);
            acc = fmaf(wih1[12], v.x, acc); acc = fmaf(wih1[13], v.y, acc);
            acc = fmaf(wih1[14], v.z, acc); acc = fmaf(wih1[15], v.w, acc);
            float4 p2 = bv[0], q2 = bv[1], u2 = bv[2], v2 = bv[3];
            acc = fmaf(whh1[ 0], p2.x, acc); acc = fmaf(whh1[ 1], p2.y, acc);
            acc = fmaf(whh1[ 2], p2.z, acc); acc = fmaf(whh1[ 3], p2.w, acc);
            acc = fmaf(whh1[ 4], q2.x, acc); acc = fmaf(whh1[ 5], q2.y, acc);
            acc = fmaf(whh1[ 6], q2.z, acc); acc = fmaf(whh1[ 7], q2.w, acc);
            acc = fmaf(whh1[ 8], u2.x, acc); acc = fmaf(whh1[ 9], u2.y, acc);
            acc = fmaf(whh1[10], u2.z, acc); acc = fmaf(whh1[11], u2.w, acc);
            acc = fmaf(whh1[12], v2.x, acc); acc = fmaf(whh1[13], v2.y, acc);
            acc = fmaf(whh1[14], v2.z, acc); acc = fmaf(whh1[15], v2.w, acc);
            acc += __shfl_xor_sync(0xffffffffu, acc, 16);
            if (kh == 0) g2[b][r] = acc;
        }
        __syncthreads();

        // ---- Phase D: layer-2 elementwise (no barrier after; safe vs A(t+1)) ----
        {
            float gi = g2[eb0][ej], gf = g2[eb0][Hn + ej];
            float gg = g2[eb0][2*Hn + ej], go = g2[eb0][3*Hn + ej];
            float i_ = sigap(gi), f_ = sigap(gf), g_ = tanhap(gg), o_ = sigap(go);
            c2a = fmaf(f_, c2a, i_ * g_);
            h2s[eb0][ej] = o_ * tanhap(c2a);

            gi = g2[eb1][ej]; gf = g2[eb1][Hn + ej];
            gg = g2[eb1][2*Hn + ej]; go = g2[eb1][3*Hn + ej];
            i_ = sigap(gi); f_ = sigap(gf); g_ = tanhap(gg); o_ = sigap(go);
            c2b = fmaf(f_, c2b, i_ * g_);
            h2s[eb1][ej] = o_ * tanhap(c2b);
        }
        // Phase D writes h2s (not read by A); A(t+1) writes g1 (B(t) finished
        // reading it before the bar after B). Two bars separate D from C(t+1).
    }
    __syncthreads();

    // ---- FC head ----
    if (tid < NB) {
        float acc = fc_b[0];
        #pragma unroll
        for (int k = 0; k < Hn; k++) acc = fmaf(h2s[tid][k], fc_w[k], acc);
        out[b0 + tid] = acc;
    }
}

extern "C" void kernel_launch(void* const* d_in, const int* in_sizes, int n_in,
                              void* d_out, int out_size)
{
    const float* x      = (const float*)d_in[0];
    const float* w_ih_0 = (const float*)d_in[1];
    const float* w_hh_0 = (const float*)d_in[2];
    const float* b_ih_0 = (const float*)d_in[3];
    const float* b_hh_0 = (const float*)d_in[4];
    const float* w_ih_1 = (const float*)d_in[5];
    const float* w_hh_1 = (const float*)d_in[6];
    const float* b_ih_1 = (const float*)d_in[7];
    const float* b_hh_1 = (const float*)d_in[8];
    const float* fc_w   = (const float*)d_in[9];
    const float* fc_b   = (const float*)d_in[10];
    float* out = (float*)d_out;

    dim3 grid(Bn / NB);   // 256 blocks -> single wave at 2 blocks/SM
    dim3 block(NT);       // 256 threads
    lstm_fused_v2<<<grid, block>>>(x, w_ih_0, w_hh_0, b_ih_0, b_hh_0,
                                   w_ih_1, w_hh_1, b_ih_1, b_hh_1,
                                   fc_w, fc_b, out);
}

// round 3
// speedup vs baseline: 3.3451x; 2.8441x over previous
#include <cuda_runtime.h>
#include <cuda_bf16.h>
#include <stdint.h>

// LSTM_558345748830 v3: tensor-core recurrence.
// Per block: 16 batches, 256 threads (8 warps). Each step:
//   gates[16][128] = h[16][K] @ W^T  via mma.m16n8k16 bf16 (2-term split, 3 passes)
// Warp w owns gate columns [16w, 16w+16). h lives in shared in A-fragment layout
// (hi+lo bf16 halves), written directly by the elementwise phase.

#define Tn 512
#define Hn 32
#define NB 16
#define NT 256
#define Bn 4096
#define GPAD 132          // gates row stride in floats

__device__ __forceinline__ float tanhap(float x) {
    float y;
    asm("tanh.approx.f32 %0, %1;" : "=f"(y) : "f"(x));
    return y;
}
__device__ __forceinline__ float sigap(float x) {
    return fmaf(tanhap(0.5f * x), 0.5f, 0.5f);
}

// D += A*B, m16n8k16, bf16 inputs, f32 accum. B col-major (= W rows contiguous in k).
__device__ __forceinline__ void mma_bf16(float* d, const uint32_t* a, const uint32_t* b) {
    asm volatile(
        "mma.sync.aligned.m16n8k16.row.col.f32.bf16.bf16.f32 "
        "{%0,%1,%2,%3}, {%4,%5,%6,%7}, {%8,%9}, {%0,%1,%2,%3};"
        : "+f"(d[0]), "+f"(d[1]), "+f"(d[2]), "+f"(d[3])
        : "r"(a[0]), "r"(a[1]), "r"(a[2]), "r"(a[3]), "r"(b[0]), "r"(b[1]));
}

// pack {even-k -> low half, odd-k -> high half}
__device__ __forceinline__ uint32_t pack2(float e_even, float e_odd) {
    uint32_t r;
    asm("cvt.rn.bf16x2.f32 %0, %1, %2;" : "=r"(r) : "f"(e_odd), "f"(e_even));
    return r;
}
__device__ __forceinline__ float bf16rt(float v) {   // round-trip through bf16
    return __bfloat162float(__float2bfloat16_rn(v));
}
__device__ __forceinline__ void split_store(uint16_t* H, uint16_t* L, int idx, float v) {
    __nv_bfloat16 bh = __float2bfloat16_rn(v);
    float fh = __bfloat162float(bh);
    __nv_bfloat16 bl = __float2bfloat16_rn(v - fh);
    H[idx] = *reinterpret_cast<uint16_t*>(&bh);
    L[idx] = *reinterpret_cast<uint16_t*>(&bl);
}

__global__ __launch_bounds__(NT, 2)
void lstm_tc(const float* __restrict__ x,
             const float* __restrict__ w_ih_0, const float* __restrict__ w_hh_0,
             const float* __restrict__ b_ih_0, const float* __restrict__ b_hh_0,
             const float* __restrict__ w_ih_1, const float* __restrict__ w_hh_1,
             const float* __restrict__ b_ih_1, const float* __restrict__ b_hh_1,
             const float* __restrict__ fc_w,   const float* __restrict__ fc_b,
             float* __restrict__ out)
{
    __shared__ float    xs[NB][Tn];        // 32 KB input slab
    __shared__ float    gts[NB][GPAD];     // gate staging (reused by both layers)
    __shared__ uint32_t fragH[4 * 4 * 32]; // A-frags (hi): ktile 0-1 = h1, 2-3 = h2
    __shared__ uint32_t fragL[4 * 4 * 32]; // A-frags (lo)
    __shared__ float    h2f[NB][Hn + 1];   // final h2 (f32) for FC head

    const int tid   = threadIdx.x;
    const int lane  = tid & 31;
    const int warp  = tid >> 5;        // 0..7
    const int g     = lane >> 2;       // mma group row 0..7
    const int t4    = lane & 3;
    const int wbase = warp * 16;       // this warp's gate-column base
    const int b0g   = blockIdx.x * NB;

    // ---- stage x slab (contiguous, coalesced) ----
    {
        const float4* src = (const float4*)(x + (size_t)b0g * Tn);
        float4* dst = (float4*)&xs[0][0];
        for (int i = tid; i < NB * Tn / 4; i += NT) dst[i] = src[i];
    }
    // ---- zero h fragments (h(0) = 0) ----
    for (int i = tid; i < 4 * 4 * 32; i += NT) { fragH[i] = 0u; fragL[i] = 0u; }

    // ---- build weight B-fragments (constant across steps) ----
    // B[k][n] col-major: b0 = {k=2t4, 2t4+1; n=g}, b1 = rows +8. low half = even k.
    uint32_t B1h[2][2][2], B1l[2][2][2];   // [ntile][ktile][b0/b1]  layer1 (W_hh_0, K=32)
    uint32_t B2h[2][4][2], B2l[2][4][2];   // layer2 ([W_ih_1 | W_hh_1], K=64)
    #pragma unroll
    for (int nt = 0; nt < 2; nt++) {
        const int n = wbase + nt * 8 + g;
        const float* w0 = w_hh_0 + n * Hn;
        #pragma unroll
        for (int kt = 0; kt < 2; kt++) {
            #pragma unroll
            for (int h = 0; h < 2; h++) {
                int k = kt * 16 + 2 * t4 + 8 * h;
                float we = w0[k], wo = w0[k + 1];
                float he = bf16rt(we), ho = bf16rt(wo);
                B1h[nt][kt][h] = pack2(he, ho);
                B1l[nt][kt][h] = pack2(we - he, wo - ho);
            }
        }
        const float* wi1 = w_ih_1 + n * Hn;
        const float* wh1 = w_hh_1 + n * Hn;
        #pragma unroll
        for (int kt = 0; kt < 4; kt++) {
            const float* ws = (kt < 2) ? (wi1 + kt * 16) : (wh1 + (kt - 2) * 16);
            #pragma unroll
            for (int h = 0; h < 2; h++) {
                int k = 2 * t4 + 8 * h;
                float we = ws[k], wo = ws[k + 1];
                float he = bf16rt(we), ho = bf16rt(wo);
                B2h[nt][kt][h] = pack2(he, ho);
                B2l[nt][kt][h] = pack2(we - he, wo - ho);
            }
        }
    }

    // ---- per-thread epilogue constants (4 gate columns: nt in {0,1} x parity) ----
    float wx[4], bi0[4], bi1[4];
    #pragma unroll
    for (int q = 0; q < 4; q++) {
        int n = wbase + (q >> 1) * 8 + 2 * t4 + (q & 1);
        wx[q]  = w_ih_0[n];
        bi0[q] = b_ih_0[n] + b_hh_0[n];
        bi1[q] = b_ih_1[n] + b_hh_1[n];
    }

    // ---- elementwise-role constants: thread handles (b = warp, lane) & (warp+8, lane) ----
    int fi1[2], fi2[2];
    {
        const int kc  = lane & 15;
        const int ktl = lane >> 4;
        const int rlo = (kc >= 8) ? 2 : 0;
        #pragma unroll
        for (int pp = 0; pp < 2; pp++) {
            int b   = warp + 8 * pp;
            int reg = rlo + ((b >= 8) ? 1 : 0);
            int ln  = (b & 7) * 4 + ((kc & 7) >> 1);
            fi1[pp] = ((ktl * 4 + reg) * 32 + ln) * 2 + (kc & 1);
            fi2[pp] = (((ktl + 2) * 4 + reg) * 32 + ln) * 2 + (kc & 1);
        }
    }
    float c1[2] = {0.f, 0.f}, c2[2] = {0.f, 0.f};

    __syncthreads();

    for (int t = 0; t < Tn; t++) {
        // ======== stage 1: load A-frags, layer-1 mma, epilogue, stage gates ========
        uint32_t Ah[4][4], Al[4][4];
        #pragma unroll
        for (int kt = 0; kt < 4; kt++) {
            #pragma unroll
            for (int r = 0; r < 4; r++) {
                Ah[kt][r] = fragH[(kt * 4 + r) * 32 + lane];
                Al[kt][r] = fragL[(kt * 4 + r) * 32 + lane];
            }
        }
        {
            float acc[2][4];
            #pragma unroll
            for (int nt = 0; nt < 2; nt++) {
                acc[nt][0] = acc[nt][1] = acc[nt][2] = acc[nt][3] = 0.f;
                #pragma unroll
                for (int kt = 0; kt < 2; kt++) {
                    mma_bf16(acc[nt], Ah[kt], B1h[nt][kt]);
                    mma_bf16(acc[nt], Al[kt], B1h[nt][kt]);
                    mma_bf16(acc[nt], Ah[kt], B1l[nt][kt]);
                }
            }
            const float xv0 = xs[g][t], xv1 = xs[g + 8][t];
            #pragma unroll
            for (int nt = 0; nt < 2; nt++) {
                #pragma unroll
                for (int p = 0; p < 2; p++) {
                    acc[nt][p]     += fmaf(wx[nt * 2 + p], xv0, bi0[nt * 2 + p]);
                    acc[nt][2 + p] += fmaf(wx[nt * 2 + p], xv1, bi0[nt * 2 + p]);
                }
                const int n0 = wbase + nt * 8 + 2 * t4;
                *(float2*)&gts[g][n0]     = make_float2(acc[nt][0], acc[nt][1]);
                *(float2*)&gts[g + 8][n0] = make_float2(acc[nt][2], acc[nt][3]);
            }
        }
        __syncthreads();

        // ======== stage 3: layer-1 elementwise -> write h1 frags (ktiles 0-1) ========
        #pragma unroll
        for (int pp = 0; pp < 2; pp++) {
            const int b = warp + 8 * pp;
            float gi = gts[b][lane],           gf = gts[b][Hn + lane];
            float gg = gts[b][2 * Hn + lane],  go = gts[b][3 * Hn + lane];
            float i_ = sigap(gi), f_ = sigap(gf), g_ = tanhap(gg), o_ = sigap(go);
            c1[pp] = fmaf(f_, c1[pp], i_ * g_);
            float hv = o_ * tanhap(c1[pp]);
            split_store((uint16_t*)fragH, (uint16_t*)fragL, fi1[pp], hv);
        }
        __syncthreads();

        // ======== stage 5: reload h1 frags, layer-2 mma, stage gates ========
        #pragma unroll
        for (int kt = 0; kt < 2; kt++) {
            #pragma unroll
            for (int r = 0; r < 4; r++) {
                Ah[kt][r] = fragH[(kt * 4 + r) * 32 + lane];
                Al[kt][r] = fragL[(kt * 4 + r) * 32 + lane];
            }
        }
        {
            float acc[2][4];
            #pragma unroll
            for (int nt = 0; nt < 2; nt++) {
                acc[nt][0] = acc[nt][1] = acc[nt][2] = acc[nt][3] = 0.f;
                #pragma unroll
                for (int kt = 0; kt < 4; kt++) {
                    mma_bf16(acc[nt], Ah[kt], B2h[nt][kt]);
                    mma_bf16(acc[nt], Al[kt], B2h[nt][kt]);
                    mma_bf16(acc[nt], Ah[kt], B2l[nt][kt]);
                }
            }
            #pragma unroll
            for (int nt = 0; nt < 2; nt++) {
                #pragma unroll
                for (int p = 0; p < 2; p++) {
                    acc[nt][p]     += bi1[nt * 2 + p];
                    acc[nt][2 + p] += bi1[nt * 2 + p];
                }
                const int n0 = wbase + nt * 8 + 2 * t4;
                *(float2*)&gts[g][n0]     = make_float2(acc[nt][0], acc[nt][1]);
                *(float2*)&gts[g + 8][n0] = make_float2(acc[nt][2], acc[nt][3]);
            }
        }
        __syncthreads();

        // ======== stage 7: layer-2 elementwise -> write h2 frags (ktiles 2-3) ========
        #pragma unroll
        for (int pp = 0; pp < 2; pp++) {
            const int b = warp + 8 * pp;
            float gi = gts[b][lane],           gf = gts[b][Hn + lane];
            float gg = gts[b][2 * Hn + lane],  go = gts[b][3 * Hn + lane];
            float i_ = sigap(gi), f_ = sigap(gf), g_ = tanhap(gg), o_ = sigap(go);
            c2[pp] = fmaf(f_, c2[pp], i_ * g_);
            float hv = o_ * tanhap(c2[pp]);
            split_store((uint16_t*)fragH, (uint16_t*)fragL, fi2[pp], hv);
            if (t == Tn - 1) h2f[b][lane] = hv;
        }
        __syncthreads();
    }

    // ---- FC head ----
    if (tid < NB) {
        float a = fc_b[0];
        #pragma unroll
        for (int k = 0; k < Hn; k++) a = fmaf(h2f[tid][k], fc_w[k], a);
        out[b0g + tid] = a;
    }
}

extern "C" void kernel_launch(void* const* d_in, const int* in_sizes, int n_in,
                              void* d_out, int out_size)
{
    (void)in_sizes; (void)n_in; (void)out_size;
    const float* x      = (const float*)d_in[0];
    const float* w_ih_0 = (const float*)d_in[1];
    const float* w_hh_0 = (const float*)d_in[2];
    const float* b_ih_0 = (const float*)d_in[3];
    const float* b_hh_0 = (const float*)d_in[4];
    const float* w_ih_1 = (const float*)d_in[5];
    const float* w_hh_1 = (const float*)d_in[6];
    const float* b_ih_1 = (const float*)d_in[7];
    const float* b_hh_1 = (const float*)d_in[8];
    const float* fc_w   = (const float*)d_in[9];
    const float* fc_b   = (const float*)d_in[10];
    float* o = (float*)d_out;

    dim3 grid(Bn / NB);   // 256 blocks, 2/SM, single wave
    dim3 block(NT);
    lstm_tc<<<grid, block>>>(x, w_ih_0, w_hh_0, b_ih_0, b_hh_0,
                             w_ih_1, w_hh_1, b_ih_1, b_hh_1,
                             fc_w, fc_b, o);
}

// round 4
// speedup vs baseline: 3.7631x; 1.1250x over previous
#include <cuda_runtime.h>
#include <cuda_bf16.h>
#include <stdint.h>

// LSTM_558345748830 v4: tensor-core recurrence, software-pipelined layers.
// Per block: 16 batches, 256 threads (8 warps). Per step only TWO barriers:
//   Phase E: h1(t) and h2(t-1) elementwise (independent) -> write A-frags
//   Phase M: gates1(t+1) and gates2(t) mma (share one frag load) -> gate bufs
// bf16 2-term split (hi/lo) mma = fp32-grade precision.

#define Tn 512
#define Hn 32
#define NB 16
#define NT 256
#define Bn 4096
#define GPAD 132          // gate-buffer row stride in floats

__device__ __forceinline__ float tanhap(float x) {
    float y;
    asm("tanh.approx.f32 %0, %1;" : "=f"(y) : "f"(x));
    return y;
}
__device__ __forceinline__ float sigap(float x) {
    return fmaf(tanhap(0.5f * x), 0.5f, 0.5f);
}

__device__ __forceinline__ void mma_bf16(float* d, const uint32_t* a, const uint32_t* b) {
    asm volatile(
        "mma.sync.aligned.m16n8k16.row.col.f32.bf16.bf16.f32 "
        "{%0,%1,%2,%3}, {%4,%5,%6,%7}, {%8,%9}, {%0,%1,%2,%3};"
        : "+f"(d[0]), "+f"(d[1]), "+f"(d[2]), "+f"(d[3])
        : "r"(a[0]), "r"(a[1]), "r"(a[2]), "r"(a[3]), "r"(b[0]), "r"(b[1]));
}

__device__ __forceinline__ uint32_t pack2(float e_even, float e_odd) {
    uint32_t r;
    asm("cvt.rn.bf16x2.f32 %0, %1, %2;" : "=r"(r) : "f"(e_odd), "f"(e_even));
    return r;
}
__device__ __forceinline__ float bf16rt(float v) {
    return __bfloat162float(__float2bfloat16_rn(v));
}
__device__ __forceinline__ void split_store(uint16_t* H, uint16_t* L, int idx, float v) {
    __nv_bfloat16 bh = __float2bfloat16_rn(v);
    float fh = __bfloat162float(bh);
    __nv_bfloat16 bl = __float2bfloat16_rn(v - fh);
    H[idx] = *reinterpret_cast<uint16_t*>(&bh);
    L[idx] = *reinterpret_cast<uint16_t*>(&bl);
}

__global__ __launch_bounds__(NT, 2)
void lstm_tc2(const float* __restrict__ x,
              const float* __restrict__ w_ih_0, const float* __restrict__ w_hh_0,
              const float* __restrict__ b_ih_0, const float* __restrict__ b_hh_0,
              const float* __restrict__ w_ih_1, const float* __restrict__ w_hh_1,
              const float* __restrict__ b_ih_1, const float* __restrict__ b_hh_1,
              const float* __restrict__ fc_w,   const float* __restrict__ fc_b,
              float* __restrict__ out)
{
    __shared__ float    gts1[NB][GPAD];    // gates1(t) staging (8.4 KB)
    __shared__ float    gts2[NB][GPAD];    // gates2(t) staging (8.4 KB)
    __shared__ uint32_t fragH[4 * 4 * 32]; // A-frags hi: kt0-1 = h1, kt2-3 = h2
    __shared__ uint32_t fragL[4 * 4 * 32]; // A-frags lo

    const int tid   = threadIdx.x;
    const int lane  = tid & 31;
    const int warp  = tid >> 5;
    const int g     = lane >> 2;
    const int t4    = lane & 3;
    const int wbase = warp * 16;
    const int b0g   = blockIdx.x * NB;
    const float* xg = x + (size_t)b0g * Tn;

    // ---- zero h fragments (h1(0-)=h2(-1)=0) ----
    for (int i = tid; i < 4 * 4 * 32; i += NT) { fragH[i] = 0u; fragL[i] = 0u; }

    // ---- weight B-fragments (hi/lo split), constant across steps ----
    uint32_t B1h[2][2][2], B1l[2][2][2];   // layer1 W_hh_0 [ntile][ktile][half]
    uint32_t B2h[2][4][2], B2l[2][4][2];   // layer2 [W_ih_1 | W_hh_1]
    #pragma unroll
    for (int nt = 0; nt < 2; nt++) {
        const int n = wbase + nt * 8 + g;
        const float* w0 = w_hh_0 + n * Hn;
        #pragma unroll
        for (int kt = 0; kt < 2; kt++) {
            #pragma unroll
            for (int h = 0; h < 2; h++) {
                int k = kt * 16 + 2 * t4 + 8 * h;
                float we = w0[k], wo = w0[k + 1];
                float he = bf16rt(we), ho = bf16rt(wo);
                B1h[nt][kt][h] = pack2(he, ho);
                B1l[nt][kt][h] = pack2(we - he, wo - ho);
            }
        }
        const float* wi1 = w_ih_1 + n * Hn;
        const float* wh1 = w_hh_1 + n * Hn;
        #pragma unroll
        for (int kt = 0; kt < 4; kt++) {
            const float* ws = (kt < 2) ? (wi1 + kt * 16) : (wh1 + (kt - 2) * 16);
            #pragma unroll
            for (int h = 0; h < 2; h++) {
                int k = 2 * t4 + 8 * h;
                float we = ws[k], wo = ws[k + 1];
                float he = bf16rt(we), ho = bf16rt(wo);
                B2h[nt][kt][h] = pack2(he, ho);
                B2l[nt][kt][h] = pack2(we - he, wo - ho);
            }
        }
    }

    // ---- epilogue constants for this thread's 4 gate columns ----
    float wx[4], bi0[4], bi1[4];
    #pragma unroll
    for (int q = 0; q < 4; q++) {
        int n = wbase + (q >> 1) * 8 + 2 * t4 + (q & 1);
        wx[q]  = w_ih_0[n];
        bi0[q] = b_ih_0[n] + b_hh_0[n];
        bi1[q] = b_ih_1[n] + b_hh_1[n];
    }

    // ---- elementwise fragment indices for (b = warp + 8pp, j = lane) ----
    int fi1[2], fi2[2];
    {
        const int kc  = lane & 15;
        const int ktl = lane >> 4;
        const int rlo = (kc >= 8) ? 2 : 0;
        #pragma unroll
        for (int pp = 0; pp < 2; pp++) {
            int b   = warp + 8 * pp;
            int reg = rlo + ((b >= 8) ? 1 : 0);
            int ln  = (b & 7) * 4 + ((kc & 7) >> 1);
            fi1[pp] = ((ktl * 4 + reg) * 32 + ln) * 2 + (kc & 1);
            fi2[pp] = (((ktl + 2) * 4 + reg) * 32 + ln) * 2 + (kc & 1);
        }
    }
    float c1[2] = {0.f, 0.f}, c2[2] = {0.f, 0.f};
    float hv2[2] = {0.f, 0.f};
    const float fw = fc_w[lane];

    // ---- prologue: gates1(0) = wx * x[:,0] + bias0 (h1(-1)=0) ----
    {
        const float xv0 = __ldg(&xg[g * Tn]);
        const float xv1 = __ldg(&xg[(g + 8) * Tn]);
        #pragma unroll
        for (int nt = 0; nt < 2; nt++) {
            const int n0 = wbase + nt * 8 + 2 * t4;
            #pragma unroll
            for (int p = 0; p < 2; p++) {
                gts1[g][n0 + p]     = fmaf(wx[nt * 2 + p], xv0, bi0[nt * 2 + p]);
                gts1[g + 8][n0 + p] = fmaf(wx[nt * 2 + p], xv1, bi0[nt * 2 + p]);
            }
        }
    }
    __syncthreads();

    for (int t = 0; t < Tn; t++) {
        // ======== Phase E: h1(t) and h2(t-1), write A-frags ========
        #pragma unroll
        for (int pp = 0; pp < 2; pp++) {
            const int b = warp + 8 * pp;
            // layer-1
            float gi = gts1[b][lane],          gf = gts1[b][Hn + lane];
            float gg = gts1[b][2 * Hn + lane], go = gts1[b][3 * Hn + lane];
            float i_ = sigap(gi), f_ = sigap(gf), g_ = tanhap(gg), o_ = sigap(go);
            c1[pp] = fmaf(f_, c1[pp], i_ * g_);
            float hv = o_ * tanhap(c1[pp]);
            split_store((uint16_t*)fragH, (uint16_t*)fragL, fi1[pp], hv);
            // layer-2 (state from previous step's gates; skip at t=0)
            if (t > 0) {
                gi = gts2[b][lane];          gf = gts2[b][Hn + lane];
                gg = gts2[b][2 * Hn + lane]; go = gts2[b][3 * Hn + lane];
                i_ = sigap(gi); f_ = sigap(gf); g_ = tanhap(gg); o_ = sigap(go);
                c2[pp] = fmaf(f_, c2[pp], i_ * g_);
                hv = o_ * tanhap(c2[pp]);
                split_store((uint16_t*)fragH, (uint16_t*)fragL, fi2[pp], hv);
            }
        }
        __syncthreads();

        // ======== Phase M: gates1(t+1) and gates2(t) ========
        uint32_t Ah[4][4], Al[4][4];
        #pragma unroll
        for (int kt = 0; kt < 4; kt++) {
            #pragma unroll
            for (int r = 0; r < 4; r++) {
                Ah[kt][r] = fragH[(kt * 4 + r) * 32 + lane];
                Al[kt][r] = fragL[(kt * 4 + r) * 32 + lane];
            }
        }
        if (t < Tn - 1) {   // gates1(t+1) = W_hh0 . h1(t) + wx*x[:,t+1] + b0
            float acc[2][4];
            #pragma unroll
            for (int nt = 0; nt < 2; nt++) {
                acc[nt][0] = acc[nt][1] = acc[nt][2] = acc[nt][3] = 0.f;
                #pragma unroll
                for (int kt = 0; kt < 2; kt++) {
                    mma_bf16(acc[nt], Ah[kt], B1h[nt][kt]);
                    mma_bf16(acc[nt], Al[kt], B1h[nt][kt]);
                    mma_bf16(acc[nt], Ah[kt], B1l[nt][kt]);
                }
            }
            const float xv0 = __ldg(&xg[g * Tn + t + 1]);
            const float xv1 = __ldg(&xg[(g + 8) * Tn + t + 1]);
            #pragma unroll
            for (int nt = 0; nt < 2; nt++) {
                const int n0 = wbase + nt * 8 + 2 * t4;
                #pragma unroll
                for (int p = 0; p < 2; p++) {
                    acc[nt][p]     += fmaf(wx[nt * 2 + p], xv0, bi0[nt * 2 + p]);
                    acc[nt][2 + p] += fmaf(wx[nt * 2 + p], xv1, bi0[nt * 2 + p]);
                }
                *(float2*)&gts1[g][n0]     = make_float2(acc[nt][0], acc[nt][1]);
                *(float2*)&gts1[g + 8][n0] = make_float2(acc[nt][2], acc[nt][3]);
            }
        }
        {   // gates2(t) = [W_ih1 | W_hh1] . [h1(t); h2(t-1)] + b1
            float acc[2][4];
            #pragma unroll
            for (int nt = 0; nt < 2; nt++) {
                acc[nt][0] = acc[nt][1] = acc[nt][2] = acc[nt][3] = 0.f;
                #pragma unroll
                for (int kt = 0; kt < 4; kt++) {
                    mma_bf16(acc[nt], Ah[kt], B2h[nt][kt]);
                    mma_bf16(acc[nt], Al[kt], B2h[nt][kt]);
                    mma_bf16(acc[nt], Ah[kt], B2l[nt][kt]);
                }
            }
            #pragma unroll
            for (int nt = 0; nt < 2; nt++) {
                const int n0 = wbase + nt * 8 + 2 * t4;
                #pragma unroll
                for (int p = 0; p < 2; p++) {
                    acc[nt][p]     += bi1[nt * 2 + p];
                    acc[nt][2 + p] += bi1[nt * 2 + p];
                }
                *(float2*)&gts2[g][n0]     = make_float2(acc[nt][0], acc[nt][1]);
                *(float2*)&gts2[g + 8][n0] = make_float2(acc[nt][2], acc[nt][3]);
            }
        }
        __syncthreads();
    }

    // ---- epilogue: h2(Tn-1) from gates2(Tn-1), then FC via shuffle reduce ----
    #pragma unroll
    for (int pp = 0; pp < 2; pp++) {
        const int b = warp + 8 * pp;
        float gi = gts2[b][lane],          gf = gts2[b][Hn + lane];
        float gg = gts2[b][2 * Hn + lane], go = gts2[b][3 * Hn + lane];
        float i_ = sigap(gi), f_ = sigap(gf), g_ = tanhap(gg), o_ = sigap(go);
        c2[pp] = fmaf(f_, c2[pp], i_ * g_);
        hv2[pp] = o_ * tanhap(c2[pp]);
    }
    #pragma unroll
    for (int pp = 0; pp < 2; pp++) {
        float prod = hv2[pp] * fw;
        #pragma unroll
        for (int off = 16; off >= 1; off >>= 1)
            prod += __shfl_xor_sync(0xffffffffu, prod, off);
        if (lane == 0) out[b0g + warp + 8 * pp] = prod + fc_b[0];
    }
}

extern "C" void kernel_launch(void* const* d_in, const int* in_sizes, int n_in,
                              void* d_out, int out_size)
{
    (void)in_sizes; (void)n_in; (void)out_size;
    const float* x      = (const float*)d_in[0];
    const float* w_ih_0 = (const float*)d_in[1];
    const float* w_hh_0 = (const float*)d_in[2];
    const float* b_ih_0 = (const float*)d_in[3];
    const float* b_hh_0 = (const float*)d_in[4];
    const float* w_ih_1 = (const float*)d_in[5];
    const float* w_hh_1 = (const float*)d_in[6];
    const float* b_ih_1 = (const float*)d_in[7];
    const float* b_hh_1 = (const float*)d_in[8];
    const float* fc_w   = (const float*)d_in[9];
    const float* fc_b   = (const float*)d_in[10];
    float* o = (float*)d_out;

    dim3 grid(Bn / NB);   // 256 blocks, 2/SM, single wave
    dim3 block(NT);
    lstm_tc2<<<grid, block>>>(x, w_ih_0, w_hh_0, b_ih_0, b_hh_0,
                              w_ih_1, w_hh_1, b_ih_1, b_hh_1,
                              fc_w, fc_b, o);
}